// round 15
// baseline (speedup 1.0000x reference)
#include <cuda_runtime.h>
#include <cuda_fp16.h>
#include <cstdint>

#define N_NODES 4096
#define HIDDEN  64
#define N_REL   8
#define N_LAYERS 2
#define NH (N_NODES * HIDDEN)

// ---------------------------------------------------------------- helpers
__device__ __forceinline__ uint32_t smem_u32(const void* p) {
    uint32_t a;
    asm("{ .reg .u64 t; cvta.to.shared.u64 t, %1; cvt.u32.u64 %0, t; }" : "=r"(a) : "l"(p));
    return a;
}

// pack two floats into f16x2 (f_even -> low half)
#define CVT_F16X2(d, f_even, f_odd) \
    asm("cvt.rn.f16x2.f32 %0, %1, %2;" : "=r"(d) : "f"(f_odd), "f"(f_even))

#define LDSM4(r, addr) \
    asm volatile("ldmatrix.sync.aligned.m8n8.x4.shared.b16 {%0,%1,%2,%3}, [%4];" \
        : "=r"((r)[0]), "=r"((r)[1]), "=r"((r)[2]), "=r"((r)[3]) : "r"(addr))

#define LDS64F(e, o, addr) \
    asm volatile("ld.shared.v2.f32 {%0,%1}, [%2];" : "=f"(e), "=f"(o) : "r"(addr))

#define MMAF16(c, a, b0, b1) \
    asm volatile("mma.sync.aligned.m16n8k16.row.col.f32.f16.f16.f32 " \
        "{%0,%1,%2,%3}, {%4,%5,%6,%7}, {%8,%9}, {%0,%1,%2,%3};" \
        : "+f"((c)[0]), "+f"((c)[1]), "+f"((c)[2]), "+f"((c)[3]) \
        : "r"((a)[0]), "r"((a)[1]), "r"((a)[2]), "r"((a)[3]), "r"(b0), "r"(b1))

#define LDGSTS16(dst, src) \
    asm volatile("cp.async.cg.shared.global [%0], [%1], 16;" :: "r"(dst), "l"(src))
#define CP_COMMIT() asm volatile("cp.async.commit_group;" ::: "memory")
#define CP_WAIT1() asm volatile("cp.async.wait_group 1;" ::: "memory")
#define CP_WAIT0() asm volatile("cp.async.wait_group 0;" ::: "memory")

// ---------------------------------------------------------------- scratch
__device__ float g_h[2][NH];                              // g_h[l] = output of layer l
__device__ float g_S[NH];
__device__ float g_part[N_REL][NH];
__device__ __half g_Yq[N_REL][HIDDEN][N_NODES];           // Y^T single fp16 [r][e][m]

// ---------------------------------------------------------------- Y / S
// Register-tiled d-blocking: 8 LDS.128 per 64 FMA (was 4 LDS + 4 LDS.128 per 16).
// Accumulation order over d preserved -> bitwise-identical results to R14.
__global__ void __launch_bounds__(256) compute_ys_kernel(
    const float* __restrict__ h,
    const float* __restrict__ w_self,
    const float* __restrict__ w_rel,
    int layer,
    __half* __restrict__ Yq,
    float* __restrict__ S)
{
    __shared__ float sbuf[8448];
    float* Ws = sbuf;
    float* Hs = sbuf + 4096;
    float* Os = sbuf + 4096;

    int m0 = blockIdx.x * 64;
    int wi = blockIdx.y;
    const float* W = (wi < N_REL)
        ? (w_rel + ((size_t)layer * N_REL + wi) * HIDDEN * HIDDEN)
        : (w_self + (size_t)layer * HIDDEN * HIDDEN);

    int tid = threadIdx.x;
    const float4* Wg = (const float4*)W;
    const float4* Hg = (const float4*)(h + (size_t)m0 * HIDDEN);
    for (int i = tid; i < 1024; i += 256) {
        ((float4*)Ws)[i] = Wg[i];
        ((float4*)Hs)[i] = Hg[i];
    }
    __syncthreads();

    int tx = tid & 15, ty = tid >> 4;
    int e0 = tx * 4;
    float acc[4][4];
    #pragma unroll
    for (int mi = 0; mi < 4; mi++)
        #pragma unroll
        for (int j = 0; j < 4; j++) acc[mi][j] = 0.f;

    #pragma unroll
    for (int d4 = 0; d4 < 16; d4++) {
        float4 hv[4];
        #pragma unroll
        for (int mi = 0; mi < 4; mi++)
            hv[mi] = *(const float4*)&Hs[(ty * 4 + mi) * HIDDEN + d4 * 4];
        #pragma unroll
        for (int dd = 0; dd < 4; dd++) {
            float4 wv = *(const float4*)&Ws[(d4 * 4 + dd) * HIDDEN + e0];
            #pragma unroll
            for (int mi = 0; mi < 4; mi++) {
                float hvv = (dd == 0) ? hv[mi].x : (dd == 1) ? hv[mi].y
                          : (dd == 2) ? hv[mi].z : hv[mi].w;
                acc[mi][0] = fmaf(hvv, wv.x, acc[mi][0]);
                acc[mi][1] = fmaf(hvv, wv.y, acc[mi][1]);
                acc[mi][2] = fmaf(hvv, wv.z, acc[mi][2]);
                acc[mi][3] = fmaf(hvv, wv.w, acc[mi][3]);
            }
        }
    }

    if (wi == N_REL) {
        #pragma unroll
        for (int mi = 0; mi < 4; mi++) {
            float4 a = make_float4(acc[mi][0], acc[mi][1], acc[mi][2], acc[mi][3]);
            *(float4*)&S[(size_t)(m0 + ty * 4 + mi) * HIDDEN + e0] = a;
        }
        return;
    }

    __syncthreads();
    #pragma unroll
    for (int mi = 0; mi < 4; mi++) {
        float4 a = make_float4(acc[mi][0], acc[mi][1], acc[mi][2], acc[mi][3]);
        *(float4*)&Os[(ty * 4 + mi) * 68 + e0] = a;
    }
    __syncthreads();

    int e   = tid >> 2;
    int seg = tid & 3;
    float v[16];
    #pragma unroll
    for (int i = 0; i < 16; i++)
        v[i] = Os[(seg * 16 + i) * 68 + e];

    uint32_t qw[8];
    #pragma unroll
    for (int j = 0; j < 8; j++)
        CVT_F16X2(qw[j], v[2 * j], v[2 * j + 1]);

    size_t off = ((size_t)wi * HIDDEN + e) * N_NODES + m0 + seg * 16;
    *(uint4*)(Yq + off)     = make_uint4(qw[0], qw[1], qw[2], qw[3]);
    *(uint4*)(Yq + off + 8) = make_uint4(qw[4], qw[5], qw[6], qw[7]);
}

// ---------------------------------------------------------------- pipelined tensor GEMM
// (unchanged from R14 — at the adj DRAM floor, ~87 us/layer)
#define KC 64
#define A_STRIDE 288
#define B_OFF 36864
#define STAGE_BYTES 45056

__device__ __forceinline__ void load_stage(
    uint32_t sbase, int stage, int mt, int tid,
    const float* Ag, const __half* Bg)
{
    const uint32_t st = sbase + stage * STAGE_BYTES;
    #pragma unroll
    for (int i = 0; i < 16; i++) {
        int c = tid + i * 128;
        int row = c >> 4, ch = c & 15;
        uint32_t dst = st + row * A_STRIDE + (((uint32_t)(ch ^ (row & 1))) << 4);
        const float* src = Ag + (size_t)row * N_NODES + mt + ch * 4;
        LDGSTS16(dst, src);
    }
    #pragma unroll
    for (int i = 0; i < 4; i++) {
        int c = tid + i * 128;
        int row = c >> 3, ch = c & 7;
        uint32_t dst = st + B_OFF + row * 128 + (((uint32_t)(ch ^ (row & 7))) << 4);
        size_t src = (size_t)row * N_NODES + mt + ch * 8;
        LDGSTS16(dst, Bg + src);
    }
}

__global__ void __launch_bounds__(128, 2) gemm_pipe_kernel(
    const float* __restrict__ adj,
    const __half* __restrict__ Yq,
    float* __restrict__ part)
{
    extern __shared__ __align__(16) char smem[];
    const int tid  = threadIdx.x;
    const int lane = tid & 31;
    const int warp_m = tid >> 5;
    const int n0 = blockIdx.x * 128;
    const int r  = blockIdx.y;
    const uint32_t sbase = smem_u32(smem);

    const float* Ag = adj + ((size_t)r << 24) + (size_t)(n0) * N_NODES;
    const __half* Bg = (const __half*)Yq + (size_t)r * HIDDEN * N_NODES;

    const int a_g = lane >> 2;
    const int a_t2 = (lane & 3) * 2;
    const int b_row_l = (lane >> 4) * 8 + (lane & 7);
    const int b_csel  = (lane >> 3) & 1;

    float c[2][8][4];
    #pragma unroll
    for (int i = 0; i < 2; i++)
        #pragma unroll
        for (int j = 0; j < 8; j++)
            #pragma unroll
            for (int k = 0; k < 4; k++) c[i][j][k] = 0.f;

    load_stage(sbase, 0, 0, tid, Ag, Bg);
    CP_COMMIT();

    #pragma unroll 1
    for (int it = 0; it < N_NODES / KC; ++it) {
        const int buf = it & 1;
        if (it < N_NODES / KC - 1) {
            load_stage(sbase, buf ^ 1, (it + 1) * KC, tid, Ag, Bg);
            CP_COMMIT();
            CP_WAIT1();
        } else {
            CP_WAIT0();
        }
        __syncthreads();

        const uint32_t st = sbase + buf * STAGE_BYTES;
        #pragma unroll
        for (int ks = 0; ks < 4; ks++) {
            uint32_t bq[4][4];
            #pragma unroll
            for (int p = 0; p < 4; p++) {
                int brow = p * 16 + b_row_l;
                uint32_t boff = brow * 128 +
                    (((uint32_t)((ks * 2 + b_csel) ^ (brow & 7))) << 4);
                LDSM4(bq[p], st + B_OFF + boff);
            }
            #pragma unroll
            for (int mi = 0; mi < 2; mi++) {
                uint32_t ah[4];
                #pragma unroll
                for (int j = 0; j < 4; j++) {
                    int row = warp_m * 32 + mi * 16 + a_g + (j & 1) * 8;
                    int k   = ks * 16 + ((j >> 1) << 3) + a_t2;
                    uint32_t addr = st + row * A_STRIDE +
                        (((uint32_t)((k >> 2) ^ (row & 1))) << 4) + (k & 3) * 4;
                    float e, o;
                    LDS64F(e, o, addr);
                    CVT_F16X2(ah[j], e, o);
                }
                #pragma unroll
                for (int p = 0; p < 4; p++) {
                    #pragma unroll
                    for (int q = 0; q < 2; q++) {
                        const int nf = p * 2 + q;
                        MMAF16(c[mi][nf], ah, bq[p][q * 2], bq[p][q * 2 + 1]);
                    }
                }
            }
        }
        __syncthreads();
    }

    float* P = part + (size_t)r * NH;
    #pragma unroll
    for (int mi = 0; mi < 2; mi++) {
        const int rbase = n0 + warp_m * 32 + mi * 16 + (lane >> 2);
        #pragma unroll
        for (int nf = 0; nf < 8; nf++) {
            const int cbase = nf * 8 + (lane & 3) * 2;
            *(float2*)&P[(size_t)rbase * HIDDEN + cbase] =
                make_float2(c[mi][nf][0], c[mi][nf][1]);
            *(float2*)&P[(size_t)(rbase + 8) * HIDDEN + cbase] =
                make_float2(c[mi][nf][2], c[mi][nf][3]);
        }
    }
}

// ---------------------------------------------------------------- finish (float4 lanes)
__global__ void finish_kernel(const float* __restrict__ S,
                              const float* __restrict__ part,
                              float* __restrict__ hn)
{
    int i = blockIdx.x * blockDim.x + threadIdx.x;   // float4 index
    if (i < NH / 4) {
        float4 v = ((const float4*)S)[i];
        #pragma unroll
        for (int r = 0; r < N_REL; r++) {
            float4 p = ((const float4*)(part + (size_t)r * NH))[i];
            v.x += p.x; v.y += p.y; v.z += p.z; v.w += p.w;
        }
        ((float4*)hn)[i] = make_float4(fmaxf(v.x, 0.f), fmaxf(v.y, 0.f),
                                       fmaxf(v.z, 0.f), fmaxf(v.w, 0.f));
    }
}

// ---------------------------------------------------------------- gather
__global__ void gather_kernel(const float* __restrict__ h,
                              const int* __restrict__ ids,
                              float* __restrict__ out)
{
    int k = blockIdx.x;
    int e = threadIdx.x;
    int id = ids[k];
    float v = (id < N_NODES) ? h[(size_t)id * HIDDEN + e] : 0.f;
    out[(size_t)k * HIDDEN + e] = v;
}

// ----------------------------------------------------------------
extern "C" void kernel_launch(void* const* d_in, const int* in_sizes, int n_in,
                              void* d_out, int out_size)
{
    const float* node_embed  = (const float*)d_in[0];
    const float* w_self      = (const float*)d_in[1];
    const float* w_rel       = (const float*)d_in[2];
    const float* rel_adj     = (const float*)d_in[3];
    const int*   keyword_ids = (const int*)d_in[4];
    float* out = (float*)d_out;

    float *h_base, *s_base, *p_base;
    __half *yq_base;
    cudaGetSymbolAddress((void**)&h_base, g_h);
    cudaGetSymbolAddress((void**)&s_base, g_S);
    cudaGetSymbolAddress((void**)&p_base, g_part);
    cudaGetSymbolAddress((void**)&yq_base, g_Yq);

    cudaFuncSetAttribute(gemm_pipe_kernel,
                         cudaFuncAttributeMaxDynamicSharedMemorySize, 2 * STAGE_BYTES);

    for (int l = 0; l < N_LAYERS; l++) {
        const float* hc = (l == 0) ? node_embed : (h_base + (size_t)(l - 1) * NH);
        float* hn = h_base + (size_t)l * NH;
        compute_ys_kernel<<<dim3(64, 9), 256>>>(hc, w_self, w_rel, l, yq_base, s_base);
        gemm_pipe_kernel<<<dim3(32, N_REL), 128, 2 * STAGE_BYTES>>>(
            rel_adj, yq_base, p_base);
        finish_kernel<<<NH / 4 / 256, 256>>>(s_base, p_base, hn);
    }

    gather_kernel<<<2048, 64>>>(h_base + NH, keyword_ids, out);
}

// round 16
// speedup vs baseline: 1.0107x; 1.0107x over previous
#include <cuda_runtime.h>
#include <cuda_fp16.h>
#include <cstdint>

#define N_NODES 4096
#define HIDDEN  64
#define N_REL   8
#define N_LAYERS 2
#define NH (N_NODES * HIDDEN)

// ---------------------------------------------------------------- helpers
__device__ __forceinline__ uint32_t smem_u32(const void* p) {
    uint32_t a;
    asm("{ .reg .u64 t; cvta.to.shared.u64 t, %1; cvt.u32.u64 %0, t; }" : "=r"(a) : "l"(p));
    return a;
}

// pack two floats into f16x2 (f_even -> low half)
#define CVT_F16X2(d, f_even, f_odd) \
    asm("cvt.rn.f16x2.f32 %0, %1, %2;" : "=r"(d) : "f"(f_odd), "f"(f_even))

#define LDSM4(r, addr) \
    asm volatile("ldmatrix.sync.aligned.m8n8.x4.shared.b16 {%0,%1,%2,%3}, [%4];" \
        : "=r"((r)[0]), "=r"((r)[1]), "=r"((r)[2]), "=r"((r)[3]) : "r"(addr))

// transposed ldmatrix: tile stored k-major (k rows, n cols) -> B fragment
#define LDSM4T(r, addr) \
    asm volatile("ldmatrix.sync.aligned.m8n8.x4.trans.shared.b16 {%0,%1,%2,%3}, [%4];" \
        : "=r"((r)[0]), "=r"((r)[1]), "=r"((r)[2]), "=r"((r)[3]) : "r"(addr))

#define LDS64F(e, o, addr) \
    asm volatile("ld.shared.v2.f32 {%0,%1}, [%2];" : "=f"(e), "=f"(o) : "r"(addr))

#define MMAF16(c, a, b0, b1) \
    asm volatile("mma.sync.aligned.m16n8k16.row.col.f32.f16.f16.f32 " \
        "{%0,%1,%2,%3}, {%4,%5,%6,%7}, {%8,%9}, {%0,%1,%2,%3};" \
        : "+f"((c)[0]), "+f"((c)[1]), "+f"((c)[2]), "+f"((c)[3]) \
        : "r"((a)[0]), "r"((a)[1]), "r"((a)[2]), "r"((a)[3]), "r"(b0), "r"(b1))

#define LDGSTS16(dst, src) \
    asm volatile("cp.async.cg.shared.global [%0], [%1], 16;" :: "r"(dst), "l"(src))
#define CP_COMMIT() asm volatile("cp.async.commit_group;" ::: "memory")
#define CP_WAIT1() asm volatile("cp.async.wait_group 1;" ::: "memory")
#define CP_WAIT0() asm volatile("cp.async.wait_group 0;" ::: "memory")

// ---------------------------------------------------------------- scratch
__device__ float g_h[2][NH];                              // g_h[l] = output of layer l
__device__ float g_S[NH];
__device__ float g_part[N_REL][NH];
__device__ __half g_Yq[N_REL][N_NODES][HIDDEN];           // Y fp16 [r][m][e]  (k-major for gemm B)

// ---------------------------------------------------------------- Y / S
// wi<8: Y[wi][m][e] fp16 via DIRECT coalesced stores (no smem transpose).
// wi==8: S = h @ w_self fp32.
__global__ void __launch_bounds__(256) compute_ys_kernel(
    const float* __restrict__ h,
    const float* __restrict__ w_self,
    const float* __restrict__ w_rel,
    int layer,
    __half* __restrict__ Yq,
    float* __restrict__ S)
{
    __shared__ float sbuf[8192];
    float* Ws = sbuf;
    float* Hs = sbuf + 4096;

    int m0 = blockIdx.x * 64;
    int wi = blockIdx.y;
    const float* W = (wi < N_REL)
        ? (w_rel + ((size_t)layer * N_REL + wi) * HIDDEN * HIDDEN)
        : (w_self + (size_t)layer * HIDDEN * HIDDEN);

    int tid = threadIdx.x;
    const float4* Wg = (const float4*)W;
    const float4* Hg = (const float4*)(h + (size_t)m0 * HIDDEN);
    for (int i = tid; i < 1024; i += 256) {
        ((float4*)Ws)[i] = Wg[i];
        ((float4*)Hs)[i] = Hg[i];
    }
    __syncthreads();

    int tx = tid & 15, ty = tid >> 4;
    int e0 = tx * 4;
    float acc[4][4];
    #pragma unroll
    for (int mi = 0; mi < 4; mi++)
        #pragma unroll
        for (int j = 0; j < 4; j++) acc[mi][j] = 0.f;

    #pragma unroll
    for (int d4 = 0; d4 < 16; d4++) {
        float4 hv[4];
        #pragma unroll
        for (int mi = 0; mi < 4; mi++)
            hv[mi] = *(const float4*)&Hs[(ty * 4 + mi) * HIDDEN + d4 * 4];
        #pragma unroll
        for (int dd = 0; dd < 4; dd++) {
            float4 wv = *(const float4*)&Ws[(d4 * 4 + dd) * HIDDEN + e0];
            #pragma unroll
            for (int mi = 0; mi < 4; mi++) {
                float hvv = (dd == 0) ? hv[mi].x : (dd == 1) ? hv[mi].y
                          : (dd == 2) ? hv[mi].z : hv[mi].w;
                acc[mi][0] = fmaf(hvv, wv.x, acc[mi][0]);
                acc[mi][1] = fmaf(hvv, wv.y, acc[mi][1]);
                acc[mi][2] = fmaf(hvv, wv.z, acc[mi][2]);
                acc[mi][3] = fmaf(hvv, wv.w, acc[mi][3]);
            }
        }
    }

    if (wi == N_REL) {
        #pragma unroll
        for (int mi = 0; mi < 4; mi++) {
            float4 a = make_float4(acc[mi][0], acc[mi][1], acc[mi][2], acc[mi][3]);
            *(float4*)&S[(size_t)(m0 + ty * 4 + mi) * HIDDEN + e0] = a;
        }
        return;
    }

    // direct fp16 stores: Y[wi][m0+ty*4+mi][e0..e0+3], 8B coalesced across tx
    #pragma unroll
    for (int mi = 0; mi < 4; mi++) {
        uint32_t q0, q1;
        CVT_F16X2(q0, acc[mi][0], acc[mi][1]);
        CVT_F16X2(q1, acc[mi][2], acc[mi][3]);
        size_t off = ((size_t)wi * N_NODES + m0 + ty * 4 + mi) * HIDDEN + e0;
        *(uint2*)(Yq + off) = make_uint2(q0, q1);
    }
}

// ---------------------------------------------------------------- pipelined tensor GEMM
// CTA 128(M) x 64(N), 4 warps, warp tile 32x64, KC=64, 2-stage cp.async.
// A fp32 in smem (288B rows, row&1 chunk-XOR) -> fp16 fragments in regs.
// B = Y[m][e] fp16, k-major (64 rows of 128B, contiguous in gmem),
// loaded with ldmatrix.trans. ONE MMA term per k16.
// Stage: A @0 (128*288 = 36864 B), B @36864 (8192 B) = 45056 B.
#define KC 64
#define A_STRIDE 288
#define B_OFF 36864
#define STAGE_BYTES 45056

__device__ __forceinline__ void load_stage(
    uint32_t sbase, int stage, int mt, int tid,
    const float* Ag, const __half* Bg)
{
    const uint32_t st = sbase + stage * STAGE_BYTES;
    // A: 128 rows x 64 fp32 = 2048 16B-chunks; 16 per thread
    #pragma unroll
    for (int i = 0; i < 16; i++) {
        int c = tid + i * 128;
        int row = c >> 4, ch = c & 15;
        uint32_t dst = st + row * A_STRIDE + (((uint32_t)(ch ^ (row & 1))) << 4);
        const float* src = Ag + (size_t)row * N_NODES + mt + ch * 4;
        LDGSTS16(dst, src);
    }
    // B: 64 k-rows (m = mt+row) x 64 fp16 (128B rows, CONTIGUOUS 8KB in gmem)
    #pragma unroll
    for (int i = 0; i < 4; i++) {
        int c = tid + i * 128;
        int row = c >> 3, ch = c & 7;
        uint32_t dst = st + B_OFF + row * 128 + (((uint32_t)(ch ^ (row & 7))) << 4);
        const __half* src = Bg + (size_t)(mt + row) * HIDDEN + ch * 8;
        LDGSTS16(dst, src);
    }
}

__global__ void __launch_bounds__(128, 2) gemm_pipe_kernel(
    const float* __restrict__ adj,
    const __half* __restrict__ Yq,
    float* __restrict__ part)
{
    extern __shared__ __align__(16) char smem[];
    const int tid  = threadIdx.x;
    const int lane = tid & 31;
    const int warp_m = tid >> 5;        // 4 m-groups of 32; warp covers all 64 N
    const int n0 = blockIdx.x * 128;
    const int r  = blockIdx.y;
    const uint32_t sbase = smem_u32(smem);

    const float* Ag = adj + ((size_t)r << 24) + (size_t)(n0) * N_NODES;
    const __half* Bg = (const __half*)Yq + (size_t)r * N_NODES * HIDDEN;

    const int a_g = lane >> 2;
    const int a_t2 = (lane & 3) * 2;
    // trans-B lane geometry: lane -> k-row within k16, and n16-half select
    const int bt_krow = (lane & 7) + ((lane >> 3) & 1) * 8;   // 0..15
    const int bt_csel = (lane >> 4) & 1;                      // n8-half within n16

    float c[2][8][4];
    #pragma unroll
    for (int i = 0; i < 2; i++)
        #pragma unroll
        for (int j = 0; j < 8; j++)
            #pragma unroll
            for (int k = 0; k < 4; k++) c[i][j][k] = 0.f;

    load_stage(sbase, 0, 0, tid, Ag, Bg);
    CP_COMMIT();

    #pragma unroll 1
    for (int it = 0; it < N_NODES / KC; ++it) {
        const int buf = it & 1;
        if (it < N_NODES / KC - 1) {
            load_stage(sbase, buf ^ 1, (it + 1) * KC, tid, Ag, Bg);
            CP_COMMIT();
            CP_WAIT1();
        } else {
            CP_WAIT0();
        }
        __syncthreads();

        const uint32_t st = sbase + buf * STAGE_BYTES;
        #pragma unroll
        for (int ks = 0; ks < 4; ks++) {
            // ---- B fragments via ldmatrix.trans: p indexes n16 groups ----
            uint32_t bq[4][4];
            const int krow = ks * 16 + bt_krow;
            const uint32_t rowbase = krow * 128;
            const uint32_t rsw = (uint32_t)(krow & 7);
            #pragma unroll
            for (int p = 0; p < 4; p++) {
                uint32_t chunk = ((uint32_t)(p * 2 + bt_csel)) ^ rsw;
                LDSM4T(bq[p], st + B_OFF + rowbase + (chunk << 4));
            }
            // ---- A fragments: LDS.64 fp32 pairs -> single fp16 ----
            #pragma unroll
            for (int mi = 0; mi < 2; mi++) {
                uint32_t ah[4];
                #pragma unroll
                for (int j = 0; j < 4; j++) {
                    int row = warp_m * 32 + mi * 16 + a_g + (j & 1) * 8;
                    int k   = ks * 16 + ((j >> 1) << 3) + a_t2;
                    uint32_t addr = st + row * A_STRIDE +
                        (((uint32_t)((k >> 2) ^ (row & 1))) << 4) + (k & 3) * 4;
                    float e, o;
                    LDS64F(e, o, addr);
                    CVT_F16X2(ah[j], e, o);
                }
                #pragma unroll
                for (int p = 0; p < 4; p++) {
                    #pragma unroll
                    for (int q = 0; q < 2; q++) {
                        const int nf = p * 2 + q;
                        MMAF16(c[mi][nf], ah, bq[p][q * 2], bq[p][q * 2 + 1]);
                    }
                }
            }
        }
        __syncthreads();
    }

    // epilogue
    float* P = part + (size_t)r * NH;
    #pragma unroll
    for (int mi = 0; mi < 2; mi++) {
        const int rbase = n0 + warp_m * 32 + mi * 16 + (lane >> 2);
        #pragma unroll
        for (int nf = 0; nf < 8; nf++) {
            const int cbase = nf * 8 + (lane & 3) * 2;
            *(float2*)&P[(size_t)rbase * HIDDEN + cbase] =
                make_float2(c[mi][nf][0], c[mi][nf][1]);
            *(float2*)&P[(size_t)(rbase + 8) * HIDDEN + cbase] =
                make_float2(c[mi][nf][2], c[mi][nf][3]);
        }
    }
}

// ---------------------------------------------------------------- finish (float4 lanes)
__global__ void finish_kernel(const float* __restrict__ S,
                              const float* __restrict__ part,
                              float* __restrict__ hn)
{
    int i = blockIdx.x * blockDim.x + threadIdx.x;   // float4 index
    if (i < NH / 4) {
        float4 v = ((const float4*)S)[i];
        #pragma unroll
        for (int r = 0; r < N_REL; r++) {
            float4 p = ((const float4*)(part + (size_t)r * NH))[i];
            v.x += p.x; v.y += p.y; v.z += p.z; v.w += p.w;
        }
        ((float4*)hn)[i] = make_float4(fmaxf(v.x, 0.f), fmaxf(v.y, 0.f),
                                       fmaxf(v.z, 0.f), fmaxf(v.w, 0.f));
    }
}

// ---------------------------------------------------------------- gather
__global__ void gather_kernel(const float* __restrict__ h,
                              const int* __restrict__ ids,
                              float* __restrict__ out)
{
    int k = blockIdx.x;
    int e = threadIdx.x;
    int id = ids[k];
    float v = (id < N_NODES) ? h[(size_t)id * HIDDEN + e] : 0.f;
    out[(size_t)k * HIDDEN + e] = v;
}

// ----------------------------------------------------------------
extern "C" void kernel_launch(void* const* d_in, const int* in_sizes, int n_in,
                              void* d_out, int out_size)
{
    const float* node_embed  = (const float*)d_in[0];
    const float* w_self      = (const float*)d_in[1];
    const float* w_rel       = (const float*)d_in[2];
    const float* rel_adj     = (const float*)d_in[3];
    const int*   keyword_ids = (const int*)d_in[4];
    float* out = (float*)d_out;

    float *h_base, *s_base, *p_base;
    __half *yq_base;
    cudaGetSymbolAddress((void**)&h_base, g_h);
    cudaGetSymbolAddress((void**)&s_base, g_S);
    cudaGetSymbolAddress((void**)&p_base, g_part);
    cudaGetSymbolAddress((void**)&yq_base, g_Yq);

    cudaFuncSetAttribute(gemm_pipe_kernel,
                         cudaFuncAttributeMaxDynamicSharedMemorySize, 2 * STAGE_BYTES);

    for (int l = 0; l < N_LAYERS; l++) {
        const float* hc = (l == 0) ? node_embed : (h_base + (size_t)(l - 1) * NH);
        float* hn = h_base + (size_t)l * NH;
        compute_ys_kernel<<<dim3(64, 9), 256>>>(hc, w_self, w_rel, l, yq_base, s_base);
        gemm_pipe_kernel<<<dim3(32, N_REL), 128, 2 * STAGE_BYTES>>>(
            rel_adj, yq_base, p_base);
        finish_kernel<<<NH / 4 / 256, 256>>>(s_base, p_base, hn);
    }

    gather_kernel<<<2048, 64>>>(h_base + NH, keyword_ids, out);
}

// round 17
// speedup vs baseline: 1.0675x; 1.0562x over previous
#include <cuda_runtime.h>
#include <cuda_fp16.h>
#include <cstdint>

#define N_NODES 4096
#define HIDDEN  64
#define N_REL   8
#define N_LAYERS 2
#define NH (N_NODES * HIDDEN)

// ---------------------------------------------------------------- helpers
__device__ __forceinline__ uint32_t smem_u32(const void* p) {
    uint32_t a;
    asm("{ .reg .u64 t; cvta.to.shared.u64 t, %1; cvt.u32.u64 %0, t; }" : "=r"(a) : "l"(p));
    return a;
}

// pack two floats into f16x2 (f_even -> low half)
#define CVT_F16X2(d, f_even, f_odd) \
    asm("cvt.rn.f16x2.f32 %0, %1, %2;" : "=r"(d) : "f"(f_odd), "f"(f_even))

// transposed ldmatrix: tile stored k-major (k rows, n cols) -> B fragment
#define LDSM4T(r, addr) \
    asm volatile("ldmatrix.sync.aligned.m8n8.x4.trans.shared.b16 {%0,%1,%2,%3}, [%4];" \
        : "=r"((r)[0]), "=r"((r)[1]), "=r"((r)[2]), "=r"((r)[3]) : "r"(addr))

#define LDS64F(e, o, addr) \
    asm volatile("ld.shared.v2.f32 {%0,%1}, [%2];" : "=f"(e), "=f"(o) : "r"(addr))

#define MMAF16(c, a, b0, b1) \
    asm volatile("mma.sync.aligned.m16n8k16.row.col.f32.f16.f16.f32 " \
        "{%0,%1,%2,%3}, {%4,%5,%6,%7}, {%8,%9}, {%0,%1,%2,%3};" \
        : "+f"((c)[0]), "+f"((c)[1]), "+f"((c)[2]), "+f"((c)[3]) \
        : "r"((a)[0]), "r"((a)[1]), "r"((a)[2]), "r"((a)[3]), "r"(b0), "r"(b1))

#define LDGSTS16(dst, src) \
    asm volatile("cp.async.cg.shared.global [%0], [%1], 16;" :: "r"(dst), "l"(src))
#define CP_COMMIT() asm volatile("cp.async.commit_group;" ::: "memory")
#define CP_WAIT1() asm volatile("cp.async.wait_group 1;" ::: "memory")
#define CP_WAIT0() asm volatile("cp.async.wait_group 0;" ::: "memory")

// ---------------------------------------------------------------- scratch
__device__ float g_h[2][NH];                              // g_h[l] = output of layer l
__device__ float g_S[NH];
__device__ float g_part[N_REL][NH];
__device__ __half g_Yq[N_REL][N_NODES][HIDDEN];           // Y fp16 [r][m][e] (k-major B)

#define A_STRIDE 288

// ---------------------------------------------------------------- Y / S on tensor cores
// grid (32, 9), block 128 (4 warps, warp tile 32x64). CTA: 128 h-rows, K=64.
// wi<8: Y[wi][m][e] = fp16(h) @ fp16(w_rel[wi]);  wi==8: S fp32.
// smem: h fp32 128x64 (288B rows, row&1 XOR) @0 ; W fp16 k-major 64x128B @36864.
#define YS_W_OFF 36864
#define YS_SMEM  45056

__global__ void __launch_bounds__(128, 2) compute_ys_tc_kernel(
    const float* __restrict__ h,
    const float* __restrict__ w_self,
    const float* __restrict__ w_rel,
    int layer,
    __half* __restrict__ Yq,
    float* __restrict__ S)
{
    extern __shared__ __align__(16) char smem[];
    const int tid  = threadIdx.x;
    const int lane = tid & 31;
    const int warp_m = tid >> 5;
    const int m0 = blockIdx.x * 128;
    const int wi = blockIdx.y;
    const uint32_t st = smem_u32(smem);

    const float* W = (wi < N_REL)
        ? (w_rel + ((size_t)layer * N_REL + wi) * HIDDEN * HIDDEN)
        : (w_self + (size_t)layer * HIDDEN * HIDDEN);

    // h tile via cp.async (contiguous rows: HIDDEN == KC)
    const float* Hg = h + (size_t)m0 * HIDDEN;
    #pragma unroll
    for (int i = 0; i < 16; i++) {
        int c = tid + i * 128;
        int row = c >> 4, ch = c & 15;
        uint32_t dst = st + row * A_STRIDE + (((uint32_t)(ch ^ (row & 1))) << 4);
        LDGSTS16(dst, Hg + (size_t)row * HIDDEN + ch * 4);
    }
    CP_COMMIT();

    // W fp32 -> fp16 k-major smem (rows d, 128B, row&7 XOR)
    #pragma unroll
    for (int i = 0; i < 4; i++) {
        int c = tid + i * 128;
        int d = c >> 3, ech = c & 7;
        float4 w0 = *(const float4*)(W + d * HIDDEN + ech * 8);
        float4 w1 = *(const float4*)(W + d * HIDDEN + ech * 8 + 4);
        uint32_t q0, q1, q2, q3;
        CVT_F16X2(q0, w0.x, w0.y);
        CVT_F16X2(q1, w0.z, w0.w);
        CVT_F16X2(q2, w1.x, w1.y);
        CVT_F16X2(q3, w1.z, w1.w);
        *(uint4*)(smem + YS_W_OFF + d * 128 + ((ech ^ (d & 7)) << 4)) =
            make_uint4(q0, q1, q2, q3);
    }
    CP_WAIT0();
    __syncthreads();

    const int a_g = lane >> 2;
    const int a_t2 = (lane & 3) * 2;
    const int bt_krow = (lane & 7) + ((lane >> 3) & 1) * 8;
    const int bt_csel = (lane >> 4) & 1;

    float c[2][8][4];
    #pragma unroll
    for (int i = 0; i < 2; i++)
        #pragma unroll
        for (int j = 0; j < 8; j++)
            #pragma unroll
            for (int k = 0; k < 4; k++) c[i][j][k] = 0.f;

    #pragma unroll
    for (int ks = 0; ks < 4; ks++) {
        uint32_t bq[4][4];
        const int krow = ks * 16 + bt_krow;
        const uint32_t rowbase = krow * 128;
        const uint32_t rsw = (uint32_t)(krow & 7);
        #pragma unroll
        for (int p = 0; p < 4; p++) {
            uint32_t chunk = ((uint32_t)(p * 2 + bt_csel)) ^ rsw;
            LDSM4T(bq[p], st + YS_W_OFF + rowbase + (chunk << 4));
        }
        #pragma unroll
        for (int mi = 0; mi < 2; mi++) {
            uint32_t ah[4];
            #pragma unroll
            for (int j = 0; j < 4; j++) {
                int row = warp_m * 32 + mi * 16 + a_g + (j & 1) * 8;
                int k   = ks * 16 + ((j >> 1) << 3) + a_t2;
                uint32_t addr = st + row * A_STRIDE +
                    (((uint32_t)((k >> 2) ^ (row & 1))) << 4) + (k & 3) * 4;
                float e, o;
                LDS64F(e, o, addr);
                CVT_F16X2(ah[j], e, o);
            }
            #pragma unroll
            for (int p = 0; p < 4; p++) {
                #pragma unroll
                for (int q = 0; q < 2; q++) {
                    const int nf = p * 2 + q;
                    MMAF16(c[mi][nf], ah, bq[p][q * 2], bq[p][q * 2 + 1]);
                }
            }
        }
    }

    if (wi < N_REL) {
        __half* Yp = Yq + (size_t)wi * N_NODES * HIDDEN;
        #pragma unroll
        for (int mi = 0; mi < 2; mi++) {
            const int rbase = m0 + warp_m * 32 + mi * 16 + (lane >> 2);
            #pragma unroll
            for (int nf = 0; nf < 8; nf++) {
                const int cbase = nf * 8 + (lane & 3) * 2;
                uint32_t q0, q1;
                CVT_F16X2(q0, c[mi][nf][0], c[mi][nf][1]);
                CVT_F16X2(q1, c[mi][nf][2], c[mi][nf][3]);
                *(uint32_t*)(Yp + (size_t)rbase * HIDDEN + cbase) = q0;
                *(uint32_t*)(Yp + (size_t)(rbase + 8) * HIDDEN + cbase) = q1;
            }
        }
    } else {
        #pragma unroll
        for (int mi = 0; mi < 2; mi++) {
            const int rbase = m0 + warp_m * 32 + mi * 16 + (lane >> 2);
            #pragma unroll
            for (int nf = 0; nf < 8; nf++) {
                const int cbase = nf * 8 + (lane & 3) * 2;
                *(float2*)&S[(size_t)rbase * HIDDEN + cbase] =
                    make_float2(c[mi][nf][0], c[mi][nf][1]);
                *(float2*)&S[(size_t)(rbase + 8) * HIDDEN + cbase] =
                    make_float2(c[mi][nf][2], c[mi][nf][3]);
            }
        }
    }
}

// ---------------------------------------------------------------- pipelined tensor GEMM
// (unchanged from R16 — at the adj DRAM floor, ~87 us/layer)
#define KC 64
#define B_OFF 36864
#define STAGE_BYTES 45056

__device__ __forceinline__ void load_stage(
    uint32_t sbase, int stage, int mt, int tid,
    const float* Ag, const __half* Bg)
{
    const uint32_t st = sbase + stage * STAGE_BYTES;
    #pragma unroll
    for (int i = 0; i < 16; i++) {
        int c = tid + i * 128;
        int row = c >> 4, ch = c & 15;
        uint32_t dst = st + row * A_STRIDE + (((uint32_t)(ch ^ (row & 1))) << 4);
        const float* src = Ag + (size_t)row * N_NODES + mt + ch * 4;
        LDGSTS16(dst, src);
    }
    #pragma unroll
    for (int i = 0; i < 4; i++) {
        int c = tid + i * 128;
        int row = c >> 3, ch = c & 7;
        uint32_t dst = st + B_OFF + row * 128 + (((uint32_t)(ch ^ (row & 7))) << 4);
        const __half* src = Bg + (size_t)(mt + row) * HIDDEN + ch * 8;
        LDGSTS16(dst, src);
    }
}

__global__ void __launch_bounds__(128, 2) gemm_pipe_kernel(
    const float* __restrict__ adj,
    const __half* __restrict__ Yq,
    float* __restrict__ part)
{
    extern __shared__ __align__(16) char smem[];
    const int tid  = threadIdx.x;
    const int lane = tid & 31;
    const int warp_m = tid >> 5;
    const int n0 = blockIdx.x * 128;
    const int r  = blockIdx.y;
    const uint32_t sbase = smem_u32(smem);

    const float* Ag = adj + ((size_t)r << 24) + (size_t)(n0) * N_NODES;
    const __half* Bg = (const __half*)Yq + (size_t)r * N_NODES * HIDDEN;

    const int a_g = lane >> 2;
    const int a_t2 = (lane & 3) * 2;
    const int bt_krow = (lane & 7) + ((lane >> 3) & 1) * 8;
    const int bt_csel = (lane >> 4) & 1;

    float c[2][8][4];
    #pragma unroll
    for (int i = 0; i < 2; i++)
        #pragma unroll
        for (int j = 0; j < 8; j++)
            #pragma unroll
            for (int k = 0; k < 4; k++) c[i][j][k] = 0.f;

    load_stage(sbase, 0, 0, tid, Ag, Bg);
    CP_COMMIT();

    #pragma unroll 1
    for (int it = 0; it < N_NODES / KC; ++it) {
        const int buf = it & 1;
        if (it < N_NODES / KC - 1) {
            load_stage(sbase, buf ^ 1, (it + 1) * KC, tid, Ag, Bg);
            CP_COMMIT();
            CP_WAIT1();
        } else {
            CP_WAIT0();
        }
        __syncthreads();

        const uint32_t st = sbase + buf * STAGE_BYTES;
        #pragma unroll
        for (int ks = 0; ks < 4; ks++) {
            uint32_t bq[4][4];
            const int krow = ks * 16 + bt_krow;
            const uint32_t rowbase = krow * 128;
            const uint32_t rsw = (uint32_t)(krow & 7);
            #pragma unroll
            for (int p = 0; p < 4; p++) {
                uint32_t chunk = ((uint32_t)(p * 2 + bt_csel)) ^ rsw;
                LDSM4T(bq[p], st + B_OFF + rowbase + (chunk << 4));
            }
            #pragma unroll
            for (int mi = 0; mi < 2; mi++) {
                uint32_t ah[4];
                #pragma unroll
                for (int j = 0; j < 4; j++) {
                    int row = warp_m * 32 + mi * 16 + a_g + (j & 1) * 8;
                    int k   = ks * 16 + ((j >> 1) << 3) + a_t2;
                    uint32_t addr = st + row * A_STRIDE +
                        (((uint32_t)((k >> 2) ^ (row & 1))) << 4) + (k & 3) * 4;
                    float e, o;
                    LDS64F(e, o, addr);
                    CVT_F16X2(ah[j], e, o);
                }
                #pragma unroll
                for (int p = 0; p < 4; p++) {
                    #pragma unroll
                    for (int q = 0; q < 2; q++) {
                        const int nf = p * 2 + q;
                        MMAF16(c[mi][nf], ah, bq[p][q * 2], bq[p][q * 2 + 1]);
                    }
                }
            }
        }
        __syncthreads();
    }

    float* P = part + (size_t)r * NH;
    #pragma unroll
    for (int mi = 0; mi < 2; mi++) {
        const int rbase = n0 + warp_m * 32 + mi * 16 + (lane >> 2);
        #pragma unroll
        for (int nf = 0; nf < 8; nf++) {
            const int cbase = nf * 8 + (lane & 3) * 2;
            *(float2*)&P[(size_t)rbase * HIDDEN + cbase] =
                make_float2(c[mi][nf][0], c[mi][nf][1]);
            *(float2*)&P[(size_t)(rbase + 8) * HIDDEN + cbase] =
                make_float2(c[mi][nf][2], c[mi][nf][3]);
        }
    }
}

// ---------------------------------------------------------------- finish (float4 lanes)
__global__ void finish_kernel(const float* __restrict__ S,
                              const float* __restrict__ part,
                              float* __restrict__ hn)
{
    int i = blockIdx.x * blockDim.x + threadIdx.x;
    if (i < NH / 4) {
        float4 v = ((const float4*)S)[i];
        #pragma unroll
        for (int r = 0; r < N_REL; r++) {
            float4 p = ((const float4*)(part + (size_t)r * NH))[i];
            v.x += p.x; v.y += p.y; v.z += p.z; v.w += p.w;
        }
        ((float4*)hn)[i] = make_float4(fmaxf(v.x, 0.f), fmaxf(v.y, 0.f),
                                       fmaxf(v.z, 0.f), fmaxf(v.w, 0.f));
    }
}

// ---------------------------------------------------------------- gather
__global__ void gather_kernel(const float* __restrict__ h,
                              const int* __restrict__ ids,
                              float* __restrict__ out)
{
    int k = blockIdx.x;
    int e = threadIdx.x;
    int id = ids[k];
    float v = (id < N_NODES) ? h[(size_t)id * HIDDEN + e] : 0.f;
    out[(size_t)k * HIDDEN + e] = v;
}

// ----------------------------------------------------------------
extern "C" void kernel_launch(void* const* d_in, const int* in_sizes, int n_in,
                              void* d_out, int out_size)
{
    const float* node_embed  = (const float*)d_in[0];
    const float* w_self      = (const float*)d_in[1];
    const float* w_rel       = (const float*)d_in[2];
    const float* rel_adj     = (const float*)d_in[3];
    const int*   keyword_ids = (const int*)d_in[4];
    float* out = (float*)d_out;

    float *h_base, *s_base, *p_base;
    __half *yq_base;
    cudaGetSymbolAddress((void**)&h_base, g_h);
    cudaGetSymbolAddress((void**)&s_base, g_S);
    cudaGetSymbolAddress((void**)&p_base, g_part);
    cudaGetSymbolAddress((void**)&yq_base, g_Yq);

    cudaFuncSetAttribute(gemm_pipe_kernel,
                         cudaFuncAttributeMaxDynamicSharedMemorySize, 2 * STAGE_BYTES);
    cudaFuncSetAttribute(compute_ys_tc_kernel,
                         cudaFuncAttributeMaxDynamicSharedMemorySize, YS_SMEM);

    for (int l = 0; l < N_LAYERS; l++) {
        const float* hc = (l == 0) ? node_embed : (h_base + (size_t)(l - 1) * NH);
        float* hn = h_base + (size_t)l * NH;
        compute_ys_tc_kernel<<<dim3(32, 9), 128, YS_SMEM>>>(
            hc, w_self, w_rel, l, yq_base, s_base);
        gemm_pipe_kernel<<<dim3(32, N_REL), 128, 2 * STAGE_BYTES>>>(
            rel_adj, yq_base, p_base);
        finish_kernel<<<NH / 4 / 256, 256>>>(s_base, p_base, hn);
    }

    gather_kernel<<<2048, 64>>>(h_base + NH, keyword_ids, out);
}